// round 8
// baseline (speedup 1.0000x reference)
#include <cuda_runtime.h>
#include <cuda_bf16.h>

// Problem constants
#define NB 32            // N
#define MODES 4
#define EYS 192          // EY_SIZE
#define EY_PLANE (EYS*EYS)          // 36864 floats
#define EY_PLANE4 (EY_PLANE/4)      // 9216 float4
#define EYROW4 (EYS/4)              // 48 float4 per Ey row
#define TOTAL 1184       // (N + 2*KNN + 1) * OUT_RES
#define NK (NB*NB)       // 1024

// Fused single kernel: R7 gather (center-out row dispatch, float4 inner loop)
// with per-CTA weight precompute into shared memory (divides off the hot loop).
// blockDim = (32, 8); grid = (10, 148).
__global__ __launch_bounds__(256) void gather_en_kernel(
    const float* __restrict__ Ey,
    const float* __restrict__ U,
    const float* __restrict__ neff,
    float* __restrict__ out)
{
    // Center-out row remap: heavy interior row-bands dispatch first.
    int byl = blockIdx.y;
    const int by = (byl & 1) ? (74 + (byl >> 1)) : (73 - (byl >> 1));

    const int lane = threadIdx.x;
    const int tid  = threadIdx.y * 32 + lane;
    const int r0   = by * 8;
    const int r    = r0 + threadIdx.y;                 // 0..1183, uniform per warp
    const int c0   = blockIdx.x * 128;
    const int c    = c0 + lane * 4;                    // 16B-aligned column
    const bool active = (c < TOTAL);

    // CTA-wide block ranges
    int iA = (r0 - 160) >> 5;       if (iA < 0) iA = 0;
    int iB = (r0 + 7) >> 5;         if (iB > NB - 1) iB = NB - 1;
    int jA = (c0 - 160) >> 5;       if (jA < 0) jA = 0;
    int jB = (c0 + 124) >> 5;       if (jB > NB - 1) jB = NB - 1;
    const int nj = jB - jA + 1;                         // <= 9
    const int ne = (iB - iA + 1) * nj;                  // <= 54 blocks

    // Per-CTA weights: w_s[e*4+m], e = (i-iA)*nj + (j-jA)
    __shared__ float w_s[54 * MODES];
    if (tid < ne * MODES) {
        const int e = tid >> 2;
        const int m = tid & 3;
        const int k = ((iA + e / nj) << 5) + jA + (e % nj);
        const float n = neff[k * MODES + m];
        w_s[tid] = U[k * MODES + m] * (n * 1.5f / (n + 1.5f));
    }
    __syncthreads();

    // Per-thread row/column contribution ranges
    int i_lo = (r - 160) >> 5; if (i_lo < 0) i_lo = 0;
    int i_hi = r >> 5;         if (i_hi > NB - 1) i_hi = NB - 1;
    int j_lo = (c - 160) >> 5; if (j_lo < 0) j_lo = 0;
    int j_hi = c >> 5;         if (j_hi > NB - 1) j_hi = NB - 1;
    if (!active) { j_lo = 1; j_hi = 0; }               // tail lanes: no loads

    const float4* __restrict__ Ey4 = reinterpret_cast<const float4*>(Ey);
    const float4* __restrict__ ws4 = reinterpret_cast<const float4*>(w_s);

    float4 acc = make_float4(0.f, 0.f, 0.f, 0.f);

    for (int i = i_lo; i <= i_hi; ++i) {
        const int x = r - (i << 5);                    // 0..191
        const long base_i = (long)(i << 5) * (MODES * EY_PLANE4) + (long)x * EYROW4;
        const int ebase = (i - iA) * nj - jA;
        for (int j = j_lo; j <= j_hi; ++j) {
            const int y4 = (c - (j << 5)) >> 2;        // 0..47 float4 within row
            const float4* p = Ey4 + base_i + (long)j * (MODES * EY_PLANE4) + y4;
            const float4 wv = ws4[ebase + j];          // LDS.128, warp-uniform bcast

            const float4 e0 = __ldg(p);
            const float4 e1 = __ldg(p + EY_PLANE4);
            const float4 e2 = __ldg(p + 2 * EY_PLANE4);
            const float4 e3 = __ldg(p + 3 * EY_PLANE4);

            acc.x += wv.x * e0.x + wv.y * e1.x + wv.z * e2.x + wv.w * e3.x;
            acc.y += wv.x * e0.y + wv.y * e1.y + wv.z * e2.y + wv.w * e3.y;
            acc.z += wv.x * e0.z + wv.y * e1.z + wv.z * e2.z + wv.w * e3.z;
            acc.w += wv.x * e0.w + wv.y * e1.w + wv.z * e2.w + wv.w * e3.w;
        }
    }

    if (active) {
        *reinterpret_cast<float4*>(out + (long)r * TOTAL + c) = acc;
    }
}

extern "C" void kernel_launch(void* const* d_in, const int* in_sizes, int n_in,
                              void* d_out, int out_size) {
    // Inputs (metadata order): hs (unused), U, neff, Ey
    const float* U    = (const float*)d_in[1];
    const float* neff = (const float*)d_in[2];
    const float* Ey   = (const float*)d_in[3];
    float* out = (float*)d_out;

    dim3 block(32, 8);
    dim3 grid((TOTAL + 127) / 128, TOTAL / 8);   // (10, 148)
    gather_en_kernel<<<grid, block>>>(Ey, U, neff, out);
}

// round 9
// speedup vs baseline: 1.0088x; 1.0088x over previous
#include <cuda_runtime.h>
#include <cuda_bf16.h>

// Problem constants
#define NB 32            // N
#define MODES 4
#define EYS 192          // EY_SIZE
#define EY_PLANE (EYS*EYS)          // 36864 floats
#define EY_PLANE4 (EY_PLANE/4)      // 9216 float4
#define EYROW4 (EYS/4)              // 48 float4 per Ey row
#define TOTAL 1184       // (N + 2*KNN + 1) * OUT_RES
#define NK (NB*NB)       // 1024

// Fused single kernel: R7 gather (center-out row dispatch, float4 inner loop)
// + per-CTA weight prologue into smem with a FIXED 6x9 window layout
// (unclamped origins -> compile-time strides, no runtime shape values).
// blockDim = (32, 8); grid = (10, 148).
__global__ __launch_bounds__(256) void gather_en_kernel(
    const float* __restrict__ Ey,
    const float* __restrict__ U,
    const float* __restrict__ neff,
    float* __restrict__ out)
{
    // Center-out row remap: heavy interior row-bands dispatch first.
    int byl = blockIdx.y;
    const int by = (byl & 1) ? (74 + (byl >> 1)) : (73 - (byl >> 1));

    const int lane = threadIdx.x;
    const int tid  = threadIdx.y * 32 + lane;
    const int r0   = by * 8;
    const int r    = r0 + threadIdx.y;                 // 0..1183, uniform per warp
    const int c0   = blockIdx.x * 128;
    const int c    = c0 + lane * 4;                    // 16B-aligned column
    const bool active = (c < TOTAL);

    // Unclamped window origins (may be negative): any contributing (i,j) of
    // this CTA satisfies i-iA0 in [0,5], j-jA0 in [0,8].
    const int iA0 = (r0 - 160) >> 5;
    const int jA0 = (c0 - 160) >> 5;

    // Fixed-shape weight window: w_s[(ii*9 + jj)*4 + m], ii<6, jj<9.
    __shared__ float w_s[6 * 9 * MODES];               // 216 floats
    if (tid < 6 * 9 * MODES) {
        const int e  = tid >> 2;                       // 0..53
        const int m  = tid & 3;
        const int ii = e / 9;                          // compile-time divisor
        const int jj = e - ii * 9;
        const int i  = iA0 + ii;
        const int j  = jA0 + jj;
        float w = 0.f;
        if ((unsigned)i < NB && (unsigned)j < NB) {
            const int k = (i << 5) + j;
            const float n = neff[k * MODES + m];
            w = U[k * MODES + m] * (n * 1.5f / (n + 1.5f));
        }
        w_s[tid] = w;
    }
    __syncthreads();

    // Per-thread contribution ranges
    int i_lo = (r - 160) >> 5; if (i_lo < 0) i_lo = 0;
    int i_hi = r >> 5;         if (i_hi > NB - 1) i_hi = NB - 1;
    int j_lo = (c - 160) >> 5; if (j_lo < 0) j_lo = 0;
    int j_hi = c >> 5;         if (j_hi > NB - 1) j_hi = NB - 1;
    if (!active) { j_lo = 1; j_hi = 0; }               // tail lanes: no loads

    const float4* __restrict__ Ey4 = reinterpret_cast<const float4*>(Ey);
    const float4* __restrict__ ws4 = reinterpret_cast<const float4*>(w_s);

    float4 acc = make_float4(0.f, 0.f, 0.f, 0.f);

    for (int i = i_lo; i <= i_hi; ++i) {
        const int x = r - (i << 5);                    // 0..191
        const long base_i = (long)(i << 5) * (MODES * EY_PLANE4) + (long)x * EYROW4;
        const int wrow = (i - iA0) * 9 - jA0;          // + j -> smem float4 index
        for (int j = j_lo; j <= j_hi; ++j) {
            const int y4 = (c - (j << 5)) >> 2;        // 0..47 float4 within row
            const float4* p = Ey4 + base_i + (long)j * (MODES * EY_PLANE4) + y4;
            const float4 wv = ws4[wrow + j];           // LDS.128, warp-uniform bcast

            const float4 e0 = __ldg(p);
            const float4 e1 = __ldg(p + EY_PLANE4);
            const float4 e2 = __ldg(p + 2 * EY_PLANE4);
            const float4 e3 = __ldg(p + 3 * EY_PLANE4);

            acc.x += wv.x * e0.x + wv.y * e1.x + wv.z * e2.x + wv.w * e3.x;
            acc.y += wv.x * e0.y + wv.y * e1.y + wv.z * e2.y + wv.w * e3.y;
            acc.z += wv.x * e0.z + wv.y * e1.z + wv.z * e2.z + wv.w * e3.z;
            acc.w += wv.x * e0.w + wv.y * e1.w + wv.z * e2.w + wv.w * e3.w;
        }
    }

    if (active) {
        *reinterpret_cast<float4*>(out + (long)r * TOTAL + c) = acc;
    }
}

extern "C" void kernel_launch(void* const* d_in, const int* in_sizes, int n_in,
                              void* d_out, int out_size) {
    // Inputs (metadata order): hs (unused), U, neff, Ey
    const float* U    = (const float*)d_in[1];
    const float* neff = (const float*)d_in[2];
    const float* Ey   = (const float*)d_in[3];
    float* out = (float*)d_out;

    dim3 block(32, 8);
    dim3 grid((TOTAL + 127) / 128, TOTAL / 8);   // (10, 148)
    gather_en_kernel<<<grid, block>>>(Ey, U, neff, out);
}